// round 1
// baseline (speedup 1.0000x reference)
#include <cuda_runtime.h>
#include <math.h>

// Problem constants
#define S_LEN   2048
#define BATCH   2
#define HID     2048
#define NHEADS  16
#define HDIM    128
#define NTOK    (BATCH * S_LEN)          // 4096

// Scratch (static device globals: allowed; no runtime allocation)
__device__ float g_Q[(size_t)NTOK * HID];   // Q projection after RoPE, (NTOK, HID)
__device__ float g_A[(size_t)NTOK * HID];   // attention output before Wo, (NTOK, HID)

// ============================================================================
// SGEMM: C[M,N] = A[M,K] @ B[K,N], all row-major fp32.
// 128x128 tile, 256 threads, 8x8 per-thread microtile, K-step 8.
// M,N,K are exact multiples of tile sizes here (4096/2048/2048) -> no guards.
// ============================================================================
__global__ __launch_bounds__(256) void sgemm128(const float* __restrict__ A,
                                                const float* __restrict__ B,
                                                float* __restrict__ C,
                                                int M, int N, int K) {
    __shared__ float As[8][128];   // A tile stored transposed: As[k][m]
    __shared__ float Bs[8][128];   // B tile natural: Bs[k][n]

    int tid = threadIdx.x;
    int tx = tid & 15;             // 0..15 -> 8 output cols each
    int ty = tid >> 4;             // 0..15 -> 8 output rows each
    int rowBase = blockIdx.y * 128;
    int colBase = blockIdx.x * 128;

    float acc[8][8];
#pragma unroll
    for (int i = 0; i < 8; i++)
#pragma unroll
        for (int j = 0; j < 8; j++) acc[i][j] = 0.f;

    // A tile load: 128 rows x 8 cols = 256 float4 -> one float4 per thread
    int arow = tid >> 1;           // 0..127
    int acol = (tid & 1) << 2;     // 0 or 4
    // B tile load: 8 rows x 128 cols = 256 float4 -> one float4 per thread
    int brow = tid >> 5;           // 0..7
    int bcol = (tid & 31) << 2;    // 0..124

    const float* Ap = A + (size_t)(rowBase + arow) * K + acol;
    const float* Bp = B + (size_t)brow * N + colBase + bcol;

    for (int k0 = 0; k0 < K; k0 += 8) {
        float4 a4 = *(const float4*)(Ap + k0);
        float4 b4 = *(const float4*)(Bp + (size_t)k0 * N);
        As[acol + 0][arow] = a4.x;
        As[acol + 1][arow] = a4.y;
        As[acol + 2][arow] = a4.z;
        As[acol + 3][arow] = a4.w;
        *(float4*)&Bs[brow][bcol] = b4;
        __syncthreads();

#pragma unroll
        for (int kk = 0; kk < 8; kk++) {
            float a[8], b[8];
            float4 a0 = *(float4*)&As[kk][ty * 8];
            float4 a1 = *(float4*)&As[kk][ty * 8 + 4];
            float4 b0 = *(float4*)&Bs[kk][tx * 8];
            float4 b1 = *(float4*)&Bs[kk][tx * 8 + 4];
            a[0]=a0.x; a[1]=a0.y; a[2]=a0.z; a[3]=a0.w;
            a[4]=a1.x; a[5]=a1.y; a[6]=a1.z; a[7]=a1.w;
            b[0]=b0.x; b[1]=b0.y; b[2]=b0.z; b[3]=b0.w;
            b[4]=b1.x; b[5]=b1.y; b[6]=b1.z; b[7]=b1.w;
#pragma unroll
            for (int i = 0; i < 8; i++)
#pragma unroll
                for (int j = 0; j < 8; j++) acc[i][j] += a[i] * b[j];
        }
        __syncthreads();
    }

    float* Cp = C + (size_t)(rowBase + ty * 8) * N + colBase + tx * 8;
#pragma unroll
    for (int i = 0; i < 8; i++) {
        *(float4*)(Cp + (size_t)i * N)     = make_float4(acc[i][0], acc[i][1], acc[i][2], acc[i][3]);
        *(float4*)(Cp + (size_t)i * N + 4) = make_float4(acc[i][4], acc[i][5], acc[i][6], acc[i][7]);
    }
}

// ============================================================================
// RoPE: in-place on Q (g_Q) and K (k_new region of d_out).
// Layout: (NTOK, H, D) row-major. One thread per (tensor, token, head, pair).
// ============================================================================
__global__ __launch_bounds__(256) void rope_kernel(float* __restrict__ Q,
                                                   float* __restrict__ Kk,
                                                   const int* __restrict__ positions) {
    int idx = blockIdx.x * 256 + threadIdx.x;   // 23 bits total
    int i   = idx & 63;                         // pair index 0..63
    int h   = (idx >> 6) & 15;
    int tok = (idx >> 10) & (NTOK - 1);
    int t   = idx >> 22;                        // 0 = Q, 1 = K
    int s   = tok & (S_LEN - 1);

    float p = (float)positions[s];
    // inv_freq computed in double then used in fp32 (matches reference within ulps)
    double invd = exp(-(double)i * (9.210340371976184 / 64.0)); // ln(10000)/64
    float th = (float)((double)p * invd);
    float sn, cs;
    sincosf(th, &sn, &cs);

    float* base = (t == 0 ? Q : Kk) + (size_t)tok * HID + h * HDIM;
    float x1 = base[i];
    float x2 = base[i + 64];
    base[i]      = x1 * cs - x2 * sn;
    base[i + 64] = x2 * cs + x1 * sn;
}

// ============================================================================
// Flash attention (fp32, causal). One block per (q-tile, head, batch).
// Br = Bc = 64, D = 128, 256 threads as a 16x16 grid.
// Score phase: each thread computes a 4x4 fragment of S = Q K^T.
// PV phase:    each thread computes a 4x8 fragment of O.
// Q/K staged transposed in smem ([d][row]) so score-phase LDS.128 reads are
// broadcast (Q) or 2-way (K). V natural [row][d]. P round-trips via smem.
// ============================================================================
#define BR 64
#define BC 64
#define TSTRIDE 68     // padded row stride for transposed Q/K and for P

__global__ __launch_bounds__(256) void flash_attn(const float* __restrict__ Q,
                                                  const float* __restrict__ Kn,
                                                  const float* __restrict__ Vn,
                                                  float* __restrict__ Aout) {
    extern __shared__ float sm[];
    float* Qt = sm;                       // [128][TSTRIDE]   (d-major, row minor)
    float* Kt = Qt + 128 * TSTRIDE;       // [128][TSTRIDE]
    float* Vs = Kt + 128 * TSTRIDE;       // [64][128]
    float* Ps = Vs + 64 * 128;            // [64][TSTRIDE]

    int tid = threadIdx.x;
    int tx = tid & 15;
    int ty = tid >> 4;
    int qt = blockIdx.x;
    int h  = blockIdx.y;
    int b  = blockIdx.z;
    int qBase = qt * BR;

    const float* Qb = Q  + (size_t)b * S_LEN * HID + h * HDIM;
    const float* Kb = Kn + (size_t)b * S_LEN * HID + h * HDIM;
    const float* Vb = Vn + (size_t)b * S_LEN * HID + h * HDIM;

    // Load Q tile transposed: 64 rows x 128 d. idx -> (g, r) with r minor so
    // smem stores across a warp are stride-1 (conflict-free).
    for (int idx = tid; idx < BR * 32; idx += 256) {
        int r = idx & 63;
        int g = idx >> 6;
        float4 v = *(const float4*)(Qb + (size_t)(qBase + r) * HID + g * 4);
        Qt[(g * 4 + 0) * TSTRIDE + r] = v.x;
        Qt[(g * 4 + 1) * TSTRIDE + r] = v.y;
        Qt[(g * 4 + 2) * TSTRIDE + r] = v.z;
        Qt[(g * 4 + 3) * TSTRIDE + r] = v.w;
    }

    float m_run[4], l_run[4], o[4][8];
#pragma unroll
    for (int i = 0; i < 4; i++) {
        m_run[i] = -3.0e38f;
        l_run[i] = 0.f;
#pragma unroll
        for (int j = 0; j < 8; j++) o[i][j] = 0.f;
    }

    const float SCALE = 0.08838834764831845f;   // 1/sqrt(128)

    for (int kt = 0; kt <= qt; kt++) {
        int kBase = kt * BC;

        // Load K tile transposed
        for (int idx = tid; idx < BC * 32; idx += 256) {
            int r = idx & 63;
            int g = idx >> 6;
            float4 v = *(const float4*)(Kb + (size_t)(kBase + r) * HID + g * 4);
            Kt[(g * 4 + 0) * TSTRIDE + r] = v.x;
            Kt[(g * 4 + 1) * TSTRIDE + r] = v.y;
            Kt[(g * 4 + 2) * TSTRIDE + r] = v.z;
            Kt[(g * 4 + 3) * TSTRIDE + r] = v.w;
        }
        // Load V tile natural (coalesced both sides)
        for (int idx = tid; idx < BC * 32; idx += 256) {
            int r = idx >> 5;
            int g = idx & 31;
            float4 v = *(const float4*)(Vb + (size_t)(kBase + r) * HID + g * 4);
            *(float4*)&Vs[r * HDIM + g * 4] = v;
        }
        __syncthreads();

        // ---- scores: S = Q K^T (4x4 fragment per thread) ----
        float s[4][4];
#pragma unroll
        for (int i = 0; i < 4; i++)
#pragma unroll
            for (int j = 0; j < 4; j++) s[i][j] = 0.f;

#pragma unroll 4
        for (int kk = 0; kk < 128; kk++) {
            float4 qv = *(float4*)&Qt[kk * TSTRIDE + ty * 4];
            float4 kv = *(float4*)&Kt[kk * TSTRIDE + tx * 4];
            float qa[4] = {qv.x, qv.y, qv.z, qv.w};
            float kb[4] = {kv.x, kv.y, kv.z, kv.w};
#pragma unroll
            for (int i = 0; i < 4; i++)
#pragma unroll
                for (int j = 0; j < 4; j++) s[i][j] += qa[i] * kb[j];
        }

        // ---- online softmax (row groups of 16 lanes sharing ty) ----
        bool diag = (kt == qt);
#pragma unroll
        for (int i = 0; i < 4; i++) {
            int qrow = qBase + ty * 4 + i;
            float mi = -3.0e38f;
#pragma unroll
            for (int j = 0; j < 4; j++) {
                float v = s[i][j] * SCALE;
                if (diag && (kBase + tx * 4 + j) > qrow) v = -1.0e30f;
                s[i][j] = v;
                mi = fmaxf(mi, v);
            }
#pragma unroll
            for (int off = 8; off >= 1; off >>= 1)
                mi = fmaxf(mi, __shfl_xor_sync(0xffffffffu, mi, off));
            float Mn = fmaxf(m_run[i], mi);
            float alpha = __expf(m_run[i] - Mn);
            float rs = 0.f;
#pragma unroll
            for (int j = 0; j < 4; j++) {
                float p = __expf(s[i][j] - Mn);
                s[i][j] = p;
                rs += p;
            }
#pragma unroll
            for (int off = 8; off >= 1; off >>= 1)
                rs += __shfl_xor_sync(0xffffffffu, rs, off);
            l_run[i] = l_run[i] * alpha + rs;
            m_run[i] = Mn;
#pragma unroll
            for (int j = 0; j < 8; j++) o[i][j] *= alpha;
            *(float4*)&Ps[(ty * 4 + i) * TSTRIDE + tx * 4] =
                make_float4(s[i][0], s[i][1], s[i][2], s[i][3]);
        }
        __syncthreads();

        // ---- O += P V (4x8 fragment per thread, cols tx*8..tx*8+7) ----
#pragma unroll 2
        for (int kk = 0; kk < 64; kk++) {
            float p0 = Ps[(ty * 4 + 0) * TSTRIDE + kk];
            float p1 = Ps[(ty * 4 + 1) * TSTRIDE + kk];
            float p2 = Ps[(ty * 4 + 2) * TSTRIDE + kk];
            float p3 = Ps[(ty * 4 + 3) * TSTRIDE + kk];
            float4 v0 = *(float4*)&Vs[kk * HDIM + tx * 8];
            float4 v1 = *(float4*)&Vs[kk * HDIM + tx * 8 + 4];
            float vv[8] = {v0.x, v0.y, v0.z, v0.w, v1.x, v1.y, v1.z, v1.w};
            float pp[4] = {p0, p1, p2, p3};
#pragma unroll
            for (int i = 0; i < 4; i++)
#pragma unroll
                for (int j = 0; j < 8; j++) o[i][j] += pp[i] * vv[j];
        }
        __syncthreads();
    }

    // ---- epilogue: normalize and write (B,S,H*D) ----
#pragma unroll
    for (int i = 0; i < 4; i++) {
        float inv = 1.f / l_run[i];
        int tok = b * S_LEN + qBase + ty * 4 + i;
        float* dst = Aout + (size_t)tok * HID + h * HDIM + tx * 8;
        *(float4*)dst       = make_float4(o[i][0] * inv, o[i][1] * inv, o[i][2] * inv, o[i][3] * inv);
        *(float4*)(dst + 4) = make_float4(o[i][4] * inv, o[i][5] * inv, o[i][6] * inv, o[i][7] * inv);
    }
}

// ============================================================================
// kernel_launch
// Inputs: [0] hidden_states (f32), [1] positions (i32), [2] Wq, [3] Wk,
//         [4] Wv, [5] Wo (all f32).
// Output: [output (NTOK*HID) | k_new (NTOK*HID) | v_new (NTOK*HID)] f32.
// ============================================================================
extern "C" void kernel_launch(void* const* d_in, const int* in_sizes, int n_in,
                              void* d_out, int out_size) {
    const float* X  = (const float*)d_in[0];
    const int*   pos = (const int*)d_in[1];
    const float* Wq = (const float*)d_in[2];
    const float* Wk = (const float*)d_in[3];
    const float* Wv = (const float*)d_in[4];
    const float* Wo = (const float*)d_in[5];

    float* out  = (float*)d_out;
    float* Kreg = out + (size_t)NTOK * HID;        // k_new region
    float* Vreg = Kreg + (size_t)NTOK * HID;       // v_new region

    float *Qs, *As;
    cudaGetSymbolAddress((void**)&Qs, g_Q);
    cudaGetSymbolAddress((void**)&As, g_A);

    dim3 gemmGrid(HID / 128, NTOK / 128);          // (16, 32)

    // Projections (K/V straight into their output regions)
    sgemm128<<<gemmGrid, 256>>>(X, Wq, Qs,   NTOK, HID, HID);
    sgemm128<<<gemmGrid, 256>>>(X, Wk, Kreg, NTOK, HID, HID);
    sgemm128<<<gemmGrid, 256>>>(X, Wv, Vreg, NTOK, HID, HID);

    // RoPE on Q and K (in place)
    rope_kernel<<<(2 * NTOK * NHEADS * 64) / 256, 256>>>(Qs, Kreg, pos);

    // Flash attention
    int smemBytes = (128 * TSTRIDE * 2 + 64 * 128 + 64 * TSTRIDE) * (int)sizeof(float);
    cudaFuncSetAttribute(flash_attn, cudaFuncAttributeMaxDynamicSharedMemorySize, smemBytes);
    flash_attn<<<dim3(S_LEN / 64, NHEADS, BATCH), 256, smemBytes>>>(Qs, Kreg, Vreg, As);

    // Output projection
    sgemm128<<<gemmGrid, 256>>>(As, Wo, out, NTOK, HID, HID);
}

// round 4
// speedup vs baseline: 1.8075x; 1.8075x over previous
#include <cuda_runtime.h>
#include <stdint.h>
#include <math.h>

// Problem constants
#define S_LEN   2048
#define BATCH   2
#define HID     2048
#define NHEADS  16
#define HDIM    128
#define NTOK    (BATCH * S_LEN)          // 4096

// Scratch (static device globals: allowed; no runtime allocation)
__device__ float g_Q[(size_t)NTOK * HID];   // Q projection after RoPE, (NTOK, HID)
__device__ float g_A[(size_t)NTOK * HID];   // attention output before Wo, (NTOK, HID)

// ============================================================================
// tf32 tensor-core GEMM: C[M,N] = A[M,K] @ B[K,N], row-major fp32 in/out.
// 128x128 block tile, 4 warps (2x2), 64x64 warp tile, mma.sync.m16n8k8.tf32.
// cp.async double-buffered smem. Padded strides: A=20 (conflict-free frag
// loads: 20*g mod 32 spans {0,20,8,28,16,4,24,12}), B=136 (8*(lane%4)+lane/4).
// M,N,K multiples of 128/128/16 here -> no guards.
// ============================================================================
#define BM 128
#define BN 128
#define BK 16
#define ASTR 20
#define BSTR 136

__device__ __forceinline__ uint32_t f2tf(float x) {
    uint32_t r;
    asm("cvt.rna.tf32.f32 %0, %1;" : "=r"(r) : "f"(x));
    return r;
}

__device__ __forceinline__ void cpasync16(void* smem, const void* g) {
    uint32_t s = (uint32_t)__cvta_generic_to_shared(smem);
    asm volatile("cp.async.cg.shared.global [%0], [%1], 16;" :: "r"(s), "l"(g));
}

__device__ __forceinline__ void mma_tf32(float* c, const uint32_t* a, const uint32_t* b) {
    asm volatile(
        "mma.sync.aligned.m16n8k8.row.col.f32.tf32.tf32.f32 "
        "{%0,%1,%2,%3}, {%4,%5,%6,%7}, {%8,%9}, {%0,%1,%2,%3};"
        : "+f"(c[0]), "+f"(c[1]), "+f"(c[2]), "+f"(c[3])
        : "r"(a[0]), "r"(a[1]), "r"(a[2]), "r"(a[3]), "r"(b[0]), "r"(b[1]));
}

__global__ __launch_bounds__(128, 2) void gemm_tf32(const float* __restrict__ A,
                                                    const float* __restrict__ B,
                                                    float* __restrict__ C,
                                                    int M, int N, int K) {
    __shared__ float As[2][BM * ASTR];
    __shared__ float Bs[2][BK * BSTR];

    int tid  = threadIdx.x;
    int lane = tid & 31;
    int w    = tid >> 5;
    int wm = (w >> 1) * 64;            // warp m offset in tile
    int wn = (w & 1) * 64;             // warp n offset in tile
    int rowBase = blockIdx.y * BM;
    int colBase = blockIdx.x * BN;

    const float* Ab = A + (size_t)rowBase * K;
    const float* Bb = B + colBase;

    float acc[4][8][4];
#pragma unroll
    for (int i = 0; i < 4; i++)
#pragma unroll
        for (int j = 0; j < 8; j++)
#pragma unroll
            for (int r = 0; r < 4; r++) acc[i][j][r] = 0.f;

    int nK = K / BK;

    // ---- prologue: stage tile 0 ----
    {
#pragma unroll
        for (int i = 0; i < 4; i++) {                  // A: 128x16 = 512 float4
            int e = i * 128 + tid;
            int r = e >> 2, c4 = e & 3;
            cpasync16(&As[0][r * ASTR + c4 * 4], Ab + (size_t)r * K + c4 * 4);
        }
#pragma unroll
        for (int i = 0; i < 4; i++) {                  // B: 16x128 = 512 float4
            int e = i * 128 + tid;
            int r = e >> 5, c4 = e & 31;
            cpasync16(&Bs[0][r * BSTR + c4 * 4], Bb + (size_t)r * N + c4 * 4);
        }
        asm volatile("cp.async.commit_group;");
    }

    for (int kt = 0; kt < nK; kt++) {
        int buf = kt & 1;
        if (kt + 1 < nK) {
            int k0 = (kt + 1) * BK;
            int nb = buf ^ 1;
#pragma unroll
            for (int i = 0; i < 4; i++) {
                int e = i * 128 + tid;
                int r = e >> 2, c4 = e & 3;
                cpasync16(&As[nb][r * ASTR + c4 * 4], Ab + (size_t)r * K + k0 + c4 * 4);
            }
#pragma unroll
            for (int i = 0; i < 4; i++) {
                int e = i * 128 + tid;
                int r = e >> 5, c4 = e & 31;
                cpasync16(&Bs[nb][r * BSTR + c4 * 4], Bb + (size_t)(k0 + r) * N + c4 * 4);
            }
            asm volatile("cp.async.commit_group;");
            asm volatile("cp.async.wait_group 1;");
        } else {
            asm volatile("cp.async.wait_group 0;");
        }
        __syncthreads();

#pragma unroll
        for (int kc = 0; kc < BK; kc += 8) {
            uint32_t af[4][4], bf[8][2];
#pragma unroll
            for (int i = 0; i < 4; i++) {
                int r0 = wm + i * 16 + (lane >> 2);
                int c0 = kc + (lane & 3);
                af[i][0] = f2tf(As[buf][r0 * ASTR + c0]);
                af[i][1] = f2tf(As[buf][(r0 + 8) * ASTR + c0]);
                af[i][2] = f2tf(As[buf][r0 * ASTR + c0 + 4]);
                af[i][3] = f2tf(As[buf][(r0 + 8) * ASTR + c0 + 4]);
            }
#pragma unroll
            for (int j = 0; j < 8; j++) {
                int col = wn + j * 8 + (lane >> 2);
                int rB  = kc + (lane & 3);
                bf[j][0] = f2tf(Bs[buf][rB * BSTR + col]);
                bf[j][1] = f2tf(Bs[buf][(rB + 4) * BSTR + col]);
            }
#pragma unroll
            for (int i = 0; i < 4; i++)
#pragma unroll
                for (int j = 0; j < 8; j++)
                    mma_tf32(acc[i][j], af[i], bf[j]);
        }
        __syncthreads();
    }

    // ---- epilogue ----
#pragma unroll
    for (int i = 0; i < 4; i++) {
#pragma unroll
        for (int j = 0; j < 8; j++) {
            int r = rowBase + wm + i * 16 + (lane >> 2);
            int c = colBase + wn + j * 8 + (lane & 3) * 2;
            *(float2*)&C[(size_t)r * N + c]       = make_float2(acc[i][j][0], acc[i][j][1]);
            *(float2*)&C[(size_t)(r + 8) * N + c] = make_float2(acc[i][j][2], acc[i][j][3]);
        }
    }
}

// ============================================================================
// RoPE: in-place on Q (g_Q) and K (k_new region of d_out).
// ============================================================================
__global__ __launch_bounds__(256) void rope_kernel(float* __restrict__ Q,
                                                   float* __restrict__ Kk,
                                                   const int* __restrict__ positions) {
    int idx = blockIdx.x * 256 + threadIdx.x;
    int i   = idx & 63;
    int h   = (idx >> 6) & 15;
    int tok = (idx >> 10) & (NTOK - 1);
    int t   = idx >> 22;                        // 0 = Q, 1 = K
    int s   = tok & (S_LEN - 1);

    float p = (float)positions[s];
    double invd = exp(-(double)i * (9.210340371976184 / 64.0)); // ln(10000)/64
    float th = (float)((double)p * invd);
    float sn, cs;
    sincosf(th, &sn, &cs);

    float* base = (t == 0 ? Q : Kk) + (size_t)tok * HID + h * HDIM;
    float x1 = base[i];
    float x2 = base[i + 64];
    base[i]      = x1 * cs - x2 * sn;
    base[i + 64] = x2 * cs + x1 * sn;
}

// ============================================================================
// Flash attention (fp32, causal). One block per (q-tile, head, batch).
// Br = Bc = 64, D = 128, 256 threads as a 16x16 grid.
// ============================================================================
#define BR 64
#define BC 64
#define TSTRIDE 68

__global__ __launch_bounds__(256) void flash_attn(const float* __restrict__ Q,
                                                  const float* __restrict__ Kn,
                                                  const float* __restrict__ Vn,
                                                  float* __restrict__ Aout) {
    extern __shared__ float sm[];
    float* Qt = sm;
    float* Kt = Qt + 128 * TSTRIDE;
    float* Vs = Kt + 128 * TSTRIDE;
    float* Ps = Vs + 64 * 128;

    int tid = threadIdx.x;
    int tx = tid & 15;
    int ty = tid >> 4;
    int qt = blockIdx.x;
    int h  = blockIdx.y;
    int b  = blockIdx.z;
    int qBase = qt * BR;

    const float* Qb = Q  + (size_t)b * S_LEN * HID + h * HDIM;
    const float* Kb = Kn + (size_t)b * S_LEN * HID + h * HDIM;
    const float* Vb = Vn + (size_t)b * S_LEN * HID + h * HDIM;

    for (int idx = tid; idx < BR * 32; idx += 256) {
        int r = idx & 63;
        int g = idx >> 6;
        float4 v = *(const float4*)(Qb + (size_t)(qBase + r) * HID + g * 4);
        Qt[(g * 4 + 0) * TSTRIDE + r] = v.x;
        Qt[(g * 4 + 1) * TSTRIDE + r] = v.y;
        Qt[(g * 4 + 2) * TSTRIDE + r] = v.z;
        Qt[(g * 4 + 3) * TSTRIDE + r] = v.w;
    }

    float m_run[4], l_run[4], o[4][8];
#pragma unroll
    for (int i = 0; i < 4; i++) {
        m_run[i] = -3.0e38f;
        l_run[i] = 0.f;
#pragma unroll
        for (int j = 0; j < 8; j++) o[i][j] = 0.f;
    }

    const float SCALE = 0.08838834764831845f;

    for (int kt = 0; kt <= qt; kt++) {
        int kBase = kt * BC;

        for (int idx = tid; idx < BC * 32; idx += 256) {
            int r = idx & 63;
            int g = idx >> 6;
            float4 v = *(const float4*)(Kb + (size_t)(kBase + r) * HID + g * 4);
            Kt[(g * 4 + 0) * TSTRIDE + r] = v.x;
            Kt[(g * 4 + 1) * TSTRIDE + r] = v.y;
            Kt[(g * 4 + 2) * TSTRIDE + r] = v.z;
            Kt[(g * 4 + 3) * TSTRIDE + r] = v.w;
        }
        for (int idx = tid; idx < BC * 32; idx += 256) {
            int r = idx >> 5;
            int g = idx & 31;
            float4 v = *(const float4*)(Vb + (size_t)(kBase + r) * HID + g * 4);
            *(float4*)&Vs[r * HDIM + g * 4] = v;
        }
        __syncthreads();

        float s[4][4];
#pragma unroll
        for (int i = 0; i < 4; i++)
#pragma unroll
            for (int j = 0; j < 4; j++) s[i][j] = 0.f;

#pragma unroll 4
        for (int kk = 0; kk < 128; kk++) {
            float4 qv = *(float4*)&Qt[kk * TSTRIDE + ty * 4];
            float4 kv = *(float4*)&Kt[kk * TSTRIDE + tx * 4];
            float qa[4] = {qv.x, qv.y, qv.z, qv.w};
            float kb[4] = {kv.x, kv.y, kv.z, kv.w};
#pragma unroll
            for (int i = 0; i < 4; i++)
#pragma unroll
                for (int j = 0; j < 4; j++) s[i][j] += qa[i] * kb[j];
        }

        bool diag = (kt == qt);
#pragma unroll
        for (int i = 0; i < 4; i++) {
            int qrow = qBase + ty * 4 + i;
            float mi = -3.0e38f;
#pragma unroll
            for (int j = 0; j < 4; j++) {
                float v = s[i][j] * SCALE;
                if (diag && (kBase + tx * 4 + j) > qrow) v = -1.0e30f;
                s[i][j] = v;
                mi = fmaxf(mi, v);
            }
#pragma unroll
            for (int off = 8; off >= 1; off >>= 1)
                mi = fmaxf(mi, __shfl_xor_sync(0xffffffffu, mi, off));
            float Mn = fmaxf(m_run[i], mi);
            float alpha = __expf(m_run[i] - Mn);
            float rs = 0.f;
#pragma unroll
            for (int j = 0; j < 4; j++) {
                float p = __expf(s[i][j] - Mn);
                s[i][j] = p;
                rs += p;
            }
#pragma unroll
            for (int off = 8; off >= 1; off >>= 1)
                rs += __shfl_xor_sync(0xffffffffu, rs, off);
            l_run[i] = l_run[i] * alpha + rs;
            m_run[i] = Mn;
#pragma unroll
            for (int j = 0; j < 8; j++) o[i][j] *= alpha;
            *(float4*)&Ps[(ty * 4 + i) * TSTRIDE + tx * 4] =
                make_float4(s[i][0], s[i][1], s[i][2], s[i][3]);
        }
        __syncthreads();

#pragma unroll 2
        for (int kk = 0; kk < 64; kk++) {
            float p0 = Ps[(ty * 4 + 0) * TSTRIDE + kk];
            float p1 = Ps[(ty * 4 + 1) * TSTRIDE + kk];
            float p2 = Ps[(ty * 4 + 2) * TSTRIDE + kk];
            float p3 = Ps[(ty * 4 + 3) * TSTRIDE + kk];
            float4 v0 = *(float4*)&Vs[kk * HDIM + tx * 8];
            float4 v1 = *(float4*)&Vs[kk * HDIM + tx * 8 + 4];
            float vv[8] = {v0.x, v0.y, v0.z, v0.w, v1.x, v1.y, v1.z, v1.w};
            float pp[4] = {p0, p1, p2, p3};
#pragma unroll
            for (int i = 0; i < 4; i++)
#pragma unroll
                for (int j = 0; j < 8; j++) o[i][j] += pp[i] * vv[j];
        }
        __syncthreads();
    }

#pragma unroll
    for (int i = 0; i < 4; i++) {
        float inv = 1.f / l_run[i];
        int tok = b * S_LEN + qBase + ty * 4 + i;
        float* dst = Aout + (size_t)tok * HID + h * HDIM + tx * 8;
        *(float4*)dst       = make_float4(o[i][0] * inv, o[i][1] * inv, o[i][2] * inv, o[i][3] * inv);
        *(float4*)(dst + 4) = make_float4(o[i][4] * inv, o[i][5] * inv, o[i][6] * inv, o[i][7] * inv);
    }
}

// ============================================================================
// kernel_launch
// ============================================================================
extern "C" void kernel_launch(void* const* d_in, const int* in_sizes, int n_in,
                              void* d_out, int out_size) {
    const float* X  = (const float*)d_in[0];
    const int*   pos = (const int*)d_in[1];
    const float* Wq = (const float*)d_in[2];
    const float* Wk = (const float*)d_in[3];
    const float* Wv = (const float*)d_in[4];
    const float* Wo = (const float*)d_in[5];

    float* out  = (float*)d_out;
    float* Kreg = out + (size_t)NTOK * HID;        // k_new region
    float* Vreg = Kreg + (size_t)NTOK * HID;       // v_new region

    float *Qs, *As;
    cudaGetSymbolAddress((void**)&Qs, g_Q);
    cudaGetSymbolAddress((void**)&As, g_A);

    dim3 gemmGrid(HID / BN, NTOK / BM);            // (16, 32)

    // Projections (K/V straight into their output regions)
    gemm_tf32<<<gemmGrid, 128>>>(X, Wq, Qs,   NTOK, HID, HID);
    gemm_tf32<<<gemmGrid, 128>>>(X, Wk, Kreg, NTOK, HID, HID);
    gemm_tf32<<<gemmGrid, 128>>>(X, Wv, Vreg, NTOK, HID, HID);

    // RoPE on Q and K (in place)
    rope_kernel<<<(2 * NTOK * NHEADS * 64) / 256, 256>>>(Qs, Kreg, pos);

    // Flash attention
    int smemBytes = (128 * TSTRIDE * 2 + 64 * 128 + 64 * TSTRIDE) * (int)sizeof(float);
    cudaFuncSetAttribute(flash_attn, cudaFuncAttributeMaxDynamicSharedMemorySize, smemBytes);
    flash_attn<<<dim3(S_LEN / 64, NHEADS, BATCH), 256, smemBytes>>>(Qs, Kreg, Vreg, As);

    // Output projection
    gemm_tf32<<<gemmGrid, 128>>>(As, Wo, out, NTOK, HID, HID);
}